// round 4
// baseline (speedup 1.0000x reference)
#include <cuda_runtime.h>
#include <math.h>

#define N_USERS 50000
#define N_ITEMS 30000
#define N_ENT   100000
#define N_REL   8
#define DIM_F   128
#define E_KG    250000
#define E_UI    1000000
#define NE_TOT  (N_REL*E_KG)

// ---------------- scratch (no dynamic allocation allowed) ----------------
__device__ float g_inv_kg[(size_t)N_REL*N_ENT];   // per-(rel,dst) 1/max(count,1)
__device__ float g_inv_ui[N_USERS];
__device__ float g_entA[(size_t)N_ENT*DIM_F];
__device__ float g_entB[(size_t)N_ENT*DIM_F];
__device__ float g_res [(size_t)N_ENT*DIM_F];
__device__ float g_uf  [(size_t)N_USERS*DIM_F];
__device__ float g_uf0 [(size_t)N_USERS*DIM_F];
__device__ float g_mean[DIM_F];

__device__ __forceinline__ void red_add_v4(float* p, float a, float b, float c, float d) {
#if defined(__CUDA_ARCH__) && (__CUDA_ARCH__ >= 900)
    asm volatile("red.global.add.v4.f32 [%0], {%1,%2,%3,%4};"
                 :: "l"(p), "f"(a), "f"(b), "f"(c), "f"(d) : "memory");
#else
    atomicAdd(p + 0, a); atomicAdd(p + 1, b);
    atomicAdd(p + 2, c); atomicAdd(p + 3, d);
#endif
}

// ---------------- kernels ----------------

// zero everything needed at the start of a replay
__global__ void k_zero_init() {
    int i = blockIdx.x * blockDim.x + threadIdx.x;
    const float4 z = make_float4(0.f, 0.f, 0.f, 0.f);
    if (i < N_ENT * 32)            ((float4*)g_entA)[i] = z;
    if (i < N_USERS * 32)          { ((float4*)g_uf)[i] = z; ((float4*)g_uf0)[i] = z; }
    if (i < (N_REL * N_ENT) / 4)   ((float4*)g_inv_kg)[i] = z;
    if (i < N_USERS / 4)           ((float4*)g_inv_ui)[i] = z;
    if (i < DIM_F / 4)             ((float4*)g_mean)[i] = z;
}

// fused degree counting for both edge sets
__global__ void k_count(const int* __restrict__ kg_dst, const int* __restrict__ ui_du) {
    int e = blockIdx.x * blockDim.x + threadIdx.x;
    if (e < NE_TOT) {
        int r = e / E_KG;
        atomicAdd(&g_inv_kg[(size_t)r * N_ENT + kg_dst[e]], 1.0f);
    } else {
        int j = e - NE_TOT;
        if (j < E_UI) atomicAdd(&g_inv_ui[ui_du[j]], 1.0f);
    }
}

__global__ void k_invert() {
    int i = blockIdx.x * blockDim.x + threadIdx.x;
    if (i < N_REL * N_ENT) {
        g_inv_kg[i] = 1.0f / fmaxf(g_inv_kg[i], 1.0f);
    } else {
        int j = i - N_REL * N_ENT;
        if (j < N_USERS) g_inv_ui[j] = 1.0f / fmaxf(g_inv_ui[j], 1.0f);
    }
}

// initial hop: relation r contributes only its 16-dim slice. 4 threads/edge (f4 each).
__global__ void __launch_bounds__(256) k_scatter16(const float* __restrict__ emb,
                            const int* __restrict__ src, const int* __restrict__ dst) {
    int t = blockIdx.x * blockDim.x + threadIdx.x;
    if (t >= NE_TOT * 4) return;
    int e = t >> 2, q = t & 3;
    int r = e / E_KG;
    int s = src[e], d = dst[e];
    int c = r * 16 + q * 4;
    float4 v = *(const float4*)(emb + (size_t)s * DIM_F + c);
    red_add_v4(g_entA + (size_t)d * DIM_F + c, v.x, v.y, v.z, v.w);
}

// entA *= inv_cnt (column-slice-wise); g_res = entA; ALSO zero entB for hop 1.
__global__ void k_scale0_zeroB() {
    int t = blockIdx.x * blockDim.x + threadIdx.x;
    if (t >= N_ENT * 32) return;
    int d = t >> 5, g = t & 31;
    int r = g >> 2;
    float w = g_inv_kg[(size_t)r * N_ENT + d];
    float4 v = ((float4*)g_entA)[t];
    v.x *= w; v.y *= w; v.z *= w; v.w *= w;
    ((float4*)g_entA)[t] = v;
    ((float4*)g_res)[t]  = v;
    ((float4*)g_entB)[t] = make_float4(0.f, 0.f, 0.f, 0.f);
}

// fused hop over all relations: warp per edge, lane covers 4 dims.
// dst[d] += src[s] * inv_cnt[r][d]
template<bool A2B>
__global__ void __launch_bounds__(256) k_hop(const int* __restrict__ src, const int* __restrict__ dst) {
    int t = blockIdx.x * blockDim.x + threadIdx.x;
    int e = t >> 5;
    if (e >= NE_TOT) return;
    int lane = t & 31;
    int r = e / E_KG;
    int s = src[e], d = dst[e];
    float w = g_inv_kg[(size_t)r * N_ENT + d];
    const float4* S = (const float4*)(A2B ? g_entA : g_entB);
    float*        D = A2B ? g_entB : g_entA;
    float4 v = S[(size_t)s * 32 + lane];
    red_add_v4(D + (size_t)d * DIM_F + lane * 4, v.x * w, v.y * w, v.z * w, v.w * w);
}

// res += entB; zero entA (prep for hop 2)
__global__ void k_addB_zeroA() {
    int i = blockIdx.x * blockDim.x + threadIdx.x;
    if (i >= N_ENT * 32) return;
    float4 a = ((float4*)g_res)[i];
    float4 b = ((float4*)g_entB)[i];
    a.x += b.x; a.y += b.y; a.z += b.z; a.w += b.w;
    ((float4*)g_res)[i] = a;
    ((float4*)g_entA)[i] = make_float4(0.f, 0.f, 0.f, 0.f);
}

// res += entA (after hop 2)
__global__ void k_addA() {
    int i = blockIdx.x * blockDim.x + threadIdx.x;
    if (i >= N_ENT * 32) return;
    float4 a = ((float4*)g_res)[i];
    float4 b = ((float4*)g_entA)[i];
    a.x += b.x; a.y += b.y; a.z += b.z; a.w += b.w;
    ((float4*)g_res)[i] = a;
}

// user aggregation: warp per UI edge; accumulate sums for user_f and user_f0
__global__ void __launch_bounds__(256) k_ui(const float* __restrict__ cf,
                     const int* __restrict__ si, const int* __restrict__ du) {
    int t = blockIdx.x * blockDim.x + threadIdx.x;
    int e = t >> 5;
    if (e >= E_UI) return;
    int lane = t & 31;
    int i = si[e], u = du[e];
    float4 v = ((const float4*)g_res)[(size_t)i * 32 + lane];
    red_add_v4(g_uf + (size_t)u * DIM_F + lane * 4, v.x, v.y, v.z, v.w);
    float4 c = ((const float4*)cf)[((size_t)N_USERS + i) * 32 + lane];
    red_add_v4(g_uf0 + (size_t)u * DIM_F + lane * 4, c.x, c.y, c.z, c.w);
}

// column sums of ent_res[:N_ITEMS]
__global__ void k_mean() {
    int col = threadIdx.x;          // blockDim = 128
    float acc = 0.f;
    for (int row = blockIdx.x; row < N_ITEMS; row += gridDim.x)
        acc += g_res[(size_t)row * DIM_F + col];
    atomicAdd(&g_mean[col], acc);
}

__global__ void k_item_out(const float* __restrict__ cf, float* __restrict__ out) {
    int t = blockIdx.x * blockDim.x + threadIdx.x;
    if (t >= N_ITEMS * 32) return;
    float4 v = ((const float4*)g_res)[t];
    float4 c = ((const float4*)cf)[(size_t)N_USERS * 32 + t];
    v.x += c.x; v.y += c.y; v.z += c.z; v.w += c.w;
    ((float4*)out)[t] = v;
}

// per-user attention + final combine: warp per user, quad-shuffle dot reductions
__global__ void k_user_out(const float* __restrict__ cf, float* __restrict__ out) {
    int t = blockIdx.x * blockDim.x + threadIdx.x;
    int u = t >> 5;
    if (u >= N_USERS) return;
    int lane = t & 31;
    float invc = g_inv_ui[u];
    float4 uf  = ((const float4*)g_uf )[(size_t)u * 32 + lane];
    float4 uf0 = ((const float4*)g_uf0)[(size_t)u * 32 + lane];
    uf.x  *= invc; uf.y  *= invc; uf.z  *= invc; uf.w  *= invc;
    uf0.x *= invc; uf0.y *= invc; uf0.z *= invc; uf0.w *= invc;
    float4 ucf = ((const float4*)cf)[(size_t)u * 32 + lane];
    float4 m   = ((const float4*)g_mean)[lane];
    const float im = 1.0f / (float)N_ITEMS;
    m.x *= im; m.y *= im; m.z *= im; m.w *= im;

    float pu = uf.x * ucf.x + uf.y * ucf.y + uf.z * ucf.z + uf.w * ucf.w;
    float pm = m.x  * ucf.x + m.y  * ucf.y + m.z  * ucf.z + m.w  * ucf.w;
    pu += __shfl_xor_sync(0xffffffffu, pu, 1, 4);
    pu += __shfl_xor_sync(0xffffffffu, pu, 2, 4);
    pm += __shfl_xor_sync(0xffffffffu, pm, 1, 4);
    pm += __shfl_xor_sync(0xffffffffu, pm, 2, 4);

    float ua  = fmaxf(pu, 0.f) + 1e-10f;
    float ma  = fmaxf(pm, 0.f) + 1e-8f;
    float att = fmaxf(ua / ma - 1.0f, 0.f) + 0.01f;   // K_ATT = 1
    float sc  = tanhf(att);

    float4 o;
    o.x = sc * uf.x + uf0.x + ucf.x;
    o.y = sc * uf.y + uf0.y + ucf.y;
    o.z = sc * uf.z + uf0.z + ucf.z;
    o.w = sc * uf.w + uf0.w + ucf.w;
    ((float4*)out)[(size_t)(N_ITEMS + u) * 32 + lane] = o;
}

// ---------------- launch ----------------
extern "C" void kernel_launch(void* const* d_in, const int* in_sizes, int n_in,
                              void* d_out, int out_size) {
    const float* all_embed = (const float*)d_in[0];
    const float* cf        = (const float*)d_in[1];
    const int*   kg_src    = (const int*)d_in[2];
    const int*   kg_dst    = (const int*)d_in[3];
    const int*   ui_si     = (const int*)d_in[4];
    const int*   ui_du     = (const int*)d_in[5];
    float*       out       = (float*)d_out;

    const int B = 256;
    auto nb = [](long long n, int b) { return (unsigned)((n + b - 1) / b); };

    k_zero_init <<<nb(N_ENT * 32, B), B>>>();
    k_count     <<<nb(NE_TOT + E_UI, B), B>>>(kg_dst, ui_du);
    k_invert    <<<nb(N_REL * N_ENT + N_USERS, B), B>>>();

    k_scatter16   <<<nb((long long)NE_TOT * 4, B), B>>>(all_embed, kg_src, kg_dst);
    k_scale0_zeroB<<<nb(N_ENT * 32, B), B>>>();

    // hop 1: A -> B
    k_hop<true>   <<<nb((long long)NE_TOT * 32, B), B>>>(kg_src, kg_dst);
    k_addB_zeroA  <<<nb(N_ENT * 32, B), B>>>();

    // hop 2: B -> A
    k_hop<false>  <<<nb((long long)NE_TOT * 32, B), B>>>(kg_src, kg_dst);
    k_addA        <<<nb(N_ENT * 32, B), B>>>();

    k_ui        <<<nb((long long)E_UI * 32, B), B>>>(cf, ui_si, ui_du);
    k_mean      <<<256, 128>>>();

    k_item_out  <<<nb(N_ITEMS * 32, B), B>>>(cf, out);
    k_user_out  <<<nb((long long)N_USERS * 32, B), B>>>(cf, out);
}

// round 7
// speedup vs baseline: 1.9190x; 1.9190x over previous
#include <cuda_runtime.h>
#include <math.h>

#define N_USERS 50000
#define N_ITEMS 30000
#define N_ENT   100000
#define N_REL   8
#define DIM_F   128
#define E_KG    250000
#define E_UI    1000000
#define NE_TOT  (N_REL*E_KG)

#define NB_KG 391   // ceil(100000/256)
#define NB_UI 196   // ceil(50000/256)

// ---------------- scratch ----------------
__device__ float g_inv_kg[(size_t)N_REL*N_ENT];
__device__ float g_inv_ui[N_USERS];
__device__ int   g_cnt_kg[N_ENT];
__device__ int   g_off_kg[N_ENT];
__device__ int   g_cur_kg[N_ENT];
__device__ int   g_cnt_ui[N_USERS];
__device__ int   g_off_ui[N_USERS];
__device__ int   g_cur_ui[N_USERS];
__device__ int   g_part_kg[512];
__device__ int   g_part_ui[512];
__device__ int   g_pay_kg[NE_TOT];   // src | (rel<<20)
__device__ int   g_pay_ui[E_UI];     // item
__device__ float g_E0 [(size_t)N_ENT*DIM_F];
__device__ float g_E1 [(size_t)N_ENT*DIM_F];
__device__ float g_res[(size_t)N_ENT*DIM_F];
__device__ float g_mean[DIM_F];

// ---------------- setup kernels ----------------
__global__ void k_zero() {
    int i = blockIdx.x * blockDim.x + threadIdx.x;
    if (i < N_REL * N_ENT) g_inv_kg[i] = 0.f;
    if (i < N_USERS)       { g_inv_ui[i] = 0.f; g_cnt_ui[i] = 0; }
    if (i < DIM_F)         g_mean[i] = 0.f;
}

__global__ void k_count(const int* __restrict__ kg_dst, const int* __restrict__ ui_du) {
    int e = blockIdx.x * blockDim.x + threadIdx.x;
    if (e < NE_TOT) {
        int r = e / E_KG, d = kg_dst[e];
        atomicAdd(&g_inv_kg[(size_t)r * N_ENT + d], 1.0f);
    } else {
        int j = e - NE_TOT;
        if (j < E_UI) {
            int u = ui_du[j];
            atomicAdd(&g_inv_ui[u], 1.0f);
            atomicAdd(&g_cnt_ui[u], 1);
        }
    }
}

// invert per-(rel,dst) counts; derive total KG degree; invert UI counts.
__global__ void k_invert() {
    int i = blockIdx.x * blockDim.x + threadIdx.x;
    if (i < N_ENT) {
        float tot = 0.f;
        #pragma unroll
        for (int r = 0; r < N_REL; r++) {
            float c = g_inv_kg[(size_t)r * N_ENT + i];
            tot += c;
            g_inv_kg[(size_t)r * N_ENT + i] = 1.0f / fmaxf(c, 1.0f);
        }
        g_cnt_kg[i] = (int)tot;
    } else {
        int j = i - N_ENT;
        if (j < N_USERS) g_inv_ui[j] = 1.0f / fmaxf(g_inv_ui[j], 1.0f);
    }
}

// ---------------- scan — device-side symbol selection (W=0: kg, W=1: ui) ----------------
// NOTE: never pass __device__ globals as kernel args from host (host-side shadow
// address, not device address — that was the R6 bug). Resolve in device code.
template<int W> __device__ __forceinline__ int*  sel_cnt()  { return W ? g_cnt_ui  : g_cnt_kg; }
template<int W> __device__ __forceinline__ int*  sel_off()  { return W ? g_off_ui  : g_off_kg; }
template<int W> __device__ __forceinline__ int*  sel_cur()  { return W ? g_cur_ui  : g_cur_kg; }
template<int W> __device__ __forceinline__ int*  sel_part() { return W ? g_part_ui : g_part_kg; }
template<int W> __device__ __forceinline__ int   sel_n()    { return W ? N_USERS   : N_ENT; }
template<int W> __device__ __forceinline__ int   sel_nb()   { return W ? NB_UI     : NB_KG; }

template<int W>
__global__ void k_scan_red() {
    __shared__ int sh[256];
    const int* cnt = sel_cnt<W>();
    int n = sel_n<W>();
    int t = threadIdx.x, i = blockIdx.x * 256 + t;
    sh[t] = (i < n) ? cnt[i] : 0;
    __syncthreads();
    for (int o = 128; o > 0; o >>= 1) {
        if (t < o) sh[t] += sh[t + o];
        __syncthreads();
    }
    if (t == 0) sel_part<W>()[blockIdx.x] = sh[0];
}

template<int W>
__global__ void k_scan_part() {
    __shared__ int sh[512];
    int* part = sel_part<W>();
    int nb = sel_nb<W>();
    int t = threadIdx.x;
    int v = (t < nb) ? part[t] : 0;
    sh[t] = v;
    __syncthreads();
    for (int o = 1; o < 512; o <<= 1) {
        int x = (t >= o) ? sh[t - o] : 0;
        __syncthreads();
        sh[t] += x;
        __syncthreads();
    }
    if (t < nb) part[t] = sh[t] - v;   // exclusive
}

template<int W>
__global__ void k_scan_write() {
    __shared__ int sh[256];
    const int* cnt = sel_cnt<W>();
    int n = sel_n<W>();
    int t = threadIdx.x, i = blockIdx.x * 256 + t;
    int v = (i < n) ? cnt[i] : 0;
    sh[t] = v;
    __syncthreads();
    for (int o = 1; o < 256; o <<= 1) {
        int x = (t >= o) ? sh[t - o] : 0;
        __syncthreads();
        sh[t] += x;
        __syncthreads();
    }
    int excl = sh[t] - v + sel_part<W>()[blockIdx.x];
    if (i < n) { sel_off<W>()[i] = excl; sel_cur<W>()[i] = excl; }
}

__global__ void k_fill_kg(const int* __restrict__ src, const int* __restrict__ dst) {
    int e = blockIdx.x * blockDim.x + threadIdx.x;
    if (e >= NE_TOT) return;
    int r = e / E_KG;
    int idx = atomicAdd(&g_cur_kg[dst[e]], 1);
    g_pay_kg[idx] = src[e] | (r << 20);
}

__global__ void k_fill_ui(const int* __restrict__ si, const int* __restrict__ du) {
    int e = blockIdx.x * blockDim.x + threadIdx.x;
    if (e >= E_UI) return;
    int idx = atomicAdd(&g_cur_ui[du[e]], 1);
    g_pay_ui[idx] = si[e];
}

// ---------------- gather kernels ----------------
// E0: warp per dst. Lane owns 4 cols; only the 4 lanes of the edge's rel slice load.
__global__ void __launch_bounds__(256) k_e0(const float* __restrict__ emb) {
    int t = blockIdx.x * blockDim.x + threadIdx.x;
    int d = t >> 5;
    if (d >= N_ENT) return;
    int lane = t & 31;
    int r_lane = lane >> 2;
    int beg = g_off_kg[d], end = beg + g_cnt_kg[d];
    float4 acc = make_float4(0.f, 0.f, 0.f, 0.f);
    for (int j = beg; j < end; j++) {
        int p = g_pay_kg[j];
        int r = p >> 20;
        if (r == r_lane) {
            int s = p & 0xFFFFF;
            float4 v = *(const float4*)(emb + (size_t)s * DIM_F + lane * 4);
            acc.x += v.x; acc.y += v.y; acc.z += v.z; acc.w += v.w;
        }
    }
    float w = g_inv_kg[(size_t)r_lane * N_ENT + d];
    acc.x *= w; acc.y *= w; acc.z *= w; acc.w *= w;
    ((float4*)g_E0)[(size_t)d * 32 + lane] = acc;
}

// hop: warp per dst, full-row gathers. PHASE 1: E0->E1.  PHASE 2: E1 -> res=E0+E1+acc.
template<int PHASE>
__global__ void __launch_bounds__(256) k_hop() {
    int t = blockIdx.x * blockDim.x + threadIdx.x;
    int d = t >> 5;
    if (d >= N_ENT) return;
    int lane = t & 31;
    const float4* IN = (const float4*)(PHASE == 1 ? g_E0 : g_E1);
    // per-rel weights broadcast from lanes 0..7
    float wv = (lane < N_REL) ? g_inv_kg[(size_t)lane * N_ENT + d] : 0.f;
    int beg = g_off_kg[d], end = beg + g_cnt_kg[d];
    float4 acc = make_float4(0.f, 0.f, 0.f, 0.f);
    int j = beg;
    for (; j + 1 < end; j += 2) {
        int p0 = g_pay_kg[j], p1 = g_pay_kg[j + 1];
        int s0 = p0 & 0xFFFFF, s1 = p1 & 0xFFFFF;
        float w0 = __shfl_sync(0xffffffffu, wv, p0 >> 20);
        float w1 = __shfl_sync(0xffffffffu, wv, p1 >> 20);
        float4 v0 = IN[(size_t)s0 * 32 + lane];
        float4 v1 = IN[(size_t)s1 * 32 + lane];
        acc.x += w0 * v0.x + w1 * v1.x;
        acc.y += w0 * v0.y + w1 * v1.y;
        acc.z += w0 * v0.z + w1 * v1.z;
        acc.w += w0 * v0.w + w1 * v1.w;
    }
    if (j < end) {
        int p0 = g_pay_kg[j];
        int s0 = p0 & 0xFFFFF;
        float w0 = __shfl_sync(0xffffffffu, wv, p0 >> 20);
        float4 v0 = IN[(size_t)s0 * 32 + lane];
        acc.x += w0 * v0.x; acc.y += w0 * v0.y;
        acc.z += w0 * v0.z; acc.w += w0 * v0.w;
    }
    if (PHASE == 1) {
        ((float4*)g_E1)[(size_t)d * 32 + lane] = acc;
    } else {
        float4 a = ((const float4*)g_E0)[(size_t)d * 32 + lane];
        float4 b = ((const float4*)g_E1)[(size_t)d * 32 + lane];
        acc.x += a.x + b.x; acc.y += a.y + b.y;
        acc.z += a.z + b.z; acc.w += a.w + b.w;
        ((float4*)g_res)[(size_t)d * 32 + lane] = acc;
    }
}

// column sums of res[:N_ITEMS]
__global__ void k_mean() {
    int col = threadIdx.x;          // blockDim = 128
    float acc = 0.f;
    for (int row = blockIdx.x; row < N_ITEMS; row += gridDim.x)
        acc += g_res[(size_t)row * DIM_F + col];
    atomicAdd(&g_mean[col], acc);
}

__global__ void k_item_out(const float* __restrict__ cf, float* __restrict__ out) {
    int t = blockIdx.x * blockDim.x + threadIdx.x;
    if (t >= N_ITEMS * 32) return;
    float4 v = ((const float4*)g_res)[t];
    float4 c = ((const float4*)cf)[(size_t)N_USERS * 32 + t];
    v.x += c.x; v.y += c.y; v.z += c.z; v.w += c.w;
    ((float4*)out)[t] = v;
}

// fused: UI gather-means + attention + final user output. Warp per user.
__global__ void __launch_bounds__(256) k_user(const float* __restrict__ cf, float* __restrict__ out) {
    int t = blockIdx.x * blockDim.x + threadIdx.x;
    int u = t >> 5;
    if (u >= N_USERS) return;
    int lane = t & 31;
    int beg = g_off_ui[u], end = beg + g_cnt_ui[u];
    float4 af  = make_float4(0.f, 0.f, 0.f, 0.f);
    float4 af0 = make_float4(0.f, 0.f, 0.f, 0.f);
    int j = beg;
    for (; j + 1 < end; j += 2) {
        int i0 = g_pay_ui[j], i1 = g_pay_ui[j + 1];
        float4 v0 = ((const float4*)g_res)[(size_t)i0 * 32 + lane];
        float4 v1 = ((const float4*)g_res)[(size_t)i1 * 32 + lane];
        float4 c0 = ((const float4*)cf)[((size_t)N_USERS + i0) * 32 + lane];
        float4 c1 = ((const float4*)cf)[((size_t)N_USERS + i1) * 32 + lane];
        af.x  += v0.x + v1.x; af.y  += v0.y + v1.y; af.z  += v0.z + v1.z; af.w  += v0.w + v1.w;
        af0.x += c0.x + c1.x; af0.y += c0.y + c1.y; af0.z += c0.z + c1.z; af0.w += c0.w + c1.w;
    }
    if (j < end) {
        int i0 = g_pay_ui[j];
        float4 v0 = ((const float4*)g_res)[(size_t)i0 * 32 + lane];
        float4 c0 = ((const float4*)cf)[((size_t)N_USERS + i0) * 32 + lane];
        af.x  += v0.x; af.y  += v0.y; af.z  += v0.z; af.w  += v0.w;
        af0.x += c0.x; af0.y += c0.y; af0.z += c0.z; af0.w += c0.w;
    }
    float invc = g_inv_ui[u];
    float4 uf  = make_float4(af.x * invc, af.y * invc, af.z * invc, af.w * invc);
    float4 uf0 = make_float4(af0.x * invc, af0.y * invc, af0.z * invc, af0.w * invc);
    float4 ucf = ((const float4*)cf)[(size_t)u * 32 + lane];
    float4 m   = ((const float4*)g_mean)[lane];
    const float im = 1.0f / (float)N_ITEMS;
    m.x *= im; m.y *= im; m.z *= im; m.w *= im;

    float pu = uf.x * ucf.x + uf.y * ucf.y + uf.z * ucf.z + uf.w * ucf.w;
    float pm = m.x  * ucf.x + m.y  * ucf.y + m.z  * ucf.z + m.w  * ucf.w;
    pu += __shfl_xor_sync(0xffffffffu, pu, 1, 4);
    pu += __shfl_xor_sync(0xffffffffu, pu, 2, 4);
    pm += __shfl_xor_sync(0xffffffffu, pm, 1, 4);
    pm += __shfl_xor_sync(0xffffffffu, pm, 2, 4);

    float ua  = fmaxf(pu, 0.f) + 1e-10f;
    float ma  = fmaxf(pm, 0.f) + 1e-8f;
    float att = fmaxf(ua / ma - 1.0f, 0.f) + 0.01f;   // K_ATT = 1
    float sc  = tanhf(att);

    float4 o;
    o.x = sc * uf.x + uf0.x + ucf.x;
    o.y = sc * uf.y + uf0.y + ucf.y;
    o.z = sc * uf.z + uf0.z + ucf.z;
    o.w = sc * uf.w + uf0.w + ucf.w;
    ((float4*)out)[(size_t)(N_ITEMS + u) * 32 + lane] = o;
}

// ---------------- launch ----------------
extern "C" void kernel_launch(void* const* d_in, const int* in_sizes, int n_in,
                              void* d_out, int out_size) {
    const float* all_embed = (const float*)d_in[0];
    const float* cf        = (const float*)d_in[1];
    const int*   kg_src    = (const int*)d_in[2];
    const int*   kg_dst    = (const int*)d_in[3];
    const int*   ui_si     = (const int*)d_in[4];
    const int*   ui_du     = (const int*)d_in[5];
    float*       out       = (float*)d_out;

    const int B = 256;
    auto nb = [](long long n, int b) { return (unsigned)((n + b - 1) / b); };

    k_zero  <<<nb(N_REL * N_ENT, B), B>>>();
    k_count <<<nb(NE_TOT + E_UI, B), B>>>(kg_dst, ui_du);
    k_invert<<<nb(N_ENT + N_USERS, B), B>>>();

    // CSR build (kg + ui) — scans resolve device symbols internally
    k_scan_red<0>  <<<NB_KG, 256>>>();
    k_scan_part<0> <<<1, 512>>>();
    k_scan_write<0><<<NB_KG, 256>>>();
    k_scan_red<1>  <<<NB_UI, 256>>>();
    k_scan_part<1> <<<1, 512>>>();
    k_scan_write<1><<<NB_UI, 256>>>();
    k_fill_kg      <<<nb(NE_TOT, B), B>>>(kg_src, kg_dst);
    k_fill_ui      <<<nb(E_UI, B), B>>>(ui_si, ui_du);

    // KG pipeline (pure gather)
    k_e0     <<<nb((long long)N_ENT * 32, B), B>>>(all_embed);
    k_hop<1> <<<nb((long long)N_ENT * 32, B), B>>>();
    k_hop<2> <<<nb((long long)N_ENT * 32, B), B>>>();

    k_mean     <<<256, 128>>>();
    k_item_out <<<nb(N_ITEMS * 32, B), B>>>(cf, out);
    k_user     <<<nb((long long)N_USERS * 32, B), B>>>(cf, out);
}